// round 3
// baseline (speedup 1.0000x reference)
#include <cuda_runtime.h>

// SoftCLDiceLoss on [8,2,1024,1024]:
//   p = sigmoid(pred), t = clip(target,0,1)
//   skel(x) = 1 - prod_{k=0..10} (1 - relu(E_k - dilate(E_{k+1}))),  E_k = erode^k(x)
//   erode = 3x3 min (pad +inf), dilate = 3x3 max (pad -inf)
//   tprec = sum(skel_p * t)/(sum(skel_p)+eps) per plane; tsens symmetric
//   loss = mean(1 - 2*tprec*tsens/(tprec+tsens+eps))

#define IMG_W    1024
#define IMG_H    1024
#define NPLANES  16            // B*C = 8*2
#define PLANE_SZ (IMG_W * IMG_H)
#define NSTEPS   11            // k = 0..10

#define TILE  32
#define HALO  2
#define RG    36               // TILE + 2*HALO
#define PITCH 37               // odd pitch, conflict-free

// Scratch (device globals; no allocations allowed).
__device__ float g_E[2][2][NPLANES * PLANE_SZ];   // [skel(p/t)][pingpong]
__device__ float g_acc[2][NPLANES * PLANE_SZ];    // running prod(1 - delta)
__device__ float g_sums[NPLANES * 4];             // {sum(sp*t), sum(sp), sum(st*p), sum(st)}

__device__ __forceinline__ float min3f(float a, float b, float c) {
    return fminf(a, fminf(b, c));
}
__device__ __forceinline__ float max3f(float a, float b, float c) {
    return fmaxf(a, fmaxf(b, c));
}
__device__ __forceinline__ float sigmoidf(float x) {
    return 1.0f / (1.0f + __expf(-x));
}

__global__ void zero_sums_kernel() {
    int i = threadIdx.x;
    if (i < NPLANES * 4) g_sums[i] = 0.0f;
}

// One morphology step k: reads E_k (k==0: transformed inputs), computes
// E_{k+1} = erode(E_k) and D = dilate(E_{k+1}) in smem, updates acc.
__global__ __launch_bounds__(256) void iter_kernel(
    const float* __restrict__ pred,
    const float* __restrict__ target,
    int k)
{
    __shared__ float A[RG * PITCH];   // E_k tile (halo 2); +1e30 outside image
    __shared__ float Bs[RG * PITCH];  // temp (rowmin, then rowmax)
    __shared__ float Cs[RG * PITCH];  // E_{k+1}; -1e30 outside image

    const int z     = blockIdx.z;        // 0..31
    const int skel  = z >> 4;            // 0 = p-skeleton, 1 = t-skeleton
    const int plane = z & 15;
    const int bx    = blockIdx.x * TILE;
    const int by    = blockIdx.y * TILE;
    const int tid   = threadIdx.y * 32 + threadIdx.x;

    const size_t pbase = (size_t)plane * PLANE_SZ;
    float* __restrict__ dst = &g_E[skel][(k + 1) & 1][pbase];
    float* __restrict__ acc = &g_acc[skel][pbase];

    // ---- Phase 1: load E_k tile (with +inf padding for erosion) ----
    if (k == 0) {
        const float* __restrict__ in = (skel ? target : pred) + pbase;
        for (int i = tid; i < RG * RG; i += 256) {
            int ly = i / RG, lx = i - ly * RG;
            int gy = by - HALO + ly, gx = bx - HALO + lx;
            float v = 1e30f;
            if ((unsigned)gy < (unsigned)IMG_H && (unsigned)gx < (unsigned)IMG_W) {
                float x = in[gy * IMG_W + gx];
                v = skel ? fminf(fmaxf(x, 0.0f), 1.0f) : sigmoidf(x);
            }
            A[ly * PITCH + lx] = v;
        }
    } else {
        const float* __restrict__ src = &g_E[skel][k & 1][pbase];
        for (int i = tid; i < RG * RG; i += 256) {
            int ly = i / RG, lx = i - ly * RG;
            int gy = by - HALO + ly, gx = bx - HALO + lx;
            float v = 1e30f;
            if ((unsigned)gy < (unsigned)IMG_H && (unsigned)gx < (unsigned)IMG_W)
                v = src[gy * IMG_W + gx];
            A[ly * PITCH + lx] = v;
        }
    }
    __syncthreads();

    // ---- Phase 2: horizontal min -> Bs, cols 1..34, rows 0..35 ----
    for (int i = tid; i < RG * 34; i += 256) {
        int ly = i / 34, lx = i - ly * 34 + 1;
        int o = ly * PITCH + lx;
        Bs[o] = min3f(A[o - 1], A[o], A[o + 1]);
    }
    __syncthreads();

    // ---- Phase 3: vertical min -> Cs = E_{k+1}, rows/cols 1..34;
    //      mask out-of-image to -inf for dilation; store interior E_{k+1} ----
    for (int i = tid; i < 34 * 34; i += 256) {
        int ly = i / 34 + 1, lx = i - (ly - 1) * 34 + 1;
        int o = ly * PITCH + lx;
        float v = min3f(Bs[o - PITCH], Bs[o], Bs[o + PITCH]);
        int gy = by - HALO + ly, gx = bx - HALO + lx;
        bool inimg = ((unsigned)gy < (unsigned)IMG_H) && ((unsigned)gx < (unsigned)IMG_W);
        if (!inimg) v = -1e30f;
        Cs[o] = v;
        if (k < NSTEPS - 1 &&
            ly >= HALO && ly < HALO + TILE && lx >= HALO && lx < HALO + TILE) {
            dst[gy * IMG_W + gx] = v;   // interior is always in-image
        }
    }
    __syncthreads();

    // ---- Phase 4: horizontal max -> Bs (reuse), cols 2..33, rows 1..34 ----
    for (int i = tid; i < 34 * 32; i += 256) {
        int ly = i / 32 + 1, lx = i - (ly - 1) * 32 + 2;
        int o = ly * PITCH + lx;
        Bs[o] = max3f(Cs[o - 1], Cs[o], Cs[o + 1]);
    }
    __syncthreads();

    // ---- Phase 5: vertical max = dilate(E_{k+1}); delta; acc update ----
    for (int i = tid; i < TILE * TILE; i += 256) {
        int ly = (i >> 5) + HALO, lx = (i & 31) + HALO;
        int o = ly * PITCH + lx;
        float D = max3f(Bs[o - PITCH], Bs[o], Bs[o + PITCH]);
        float a = A[o];
        float delta = fmaxf(a - D, 0.0f);
        int gy = by + ly - HALO, gx = bx + lx - HALO;
        size_t g = (size_t)gy * IMG_W + gx;
        float m = 1.0f - delta;
        acc[g] = (k == 0) ? m : acc[g] * m;
    }
}

// Per-plane partial sums: {sum(skel_p*t), sum(skel_p), sum(skel_t*p), sum(skel_t)}
__global__ __launch_bounds__(256) void reduce_kernel(
    const float* __restrict__ pred,
    const float* __restrict__ target)
{
    const int plane = blockIdx.y;
    const size_t base = (size_t)plane * PLANE_SZ;
    float s1 = 0.f, s2 = 0.f, s3 = 0.f, s4 = 0.f;

    for (int i = blockIdx.x * 256 + threadIdx.x; i < PLANE_SZ; i += 256 * 256) {
        float p  = sigmoidf(pred[base + i]);
        float t  = target[base + i];
        float sp = 1.0f - g_acc[0][base + i];
        float st = 1.0f - g_acc[1][base + i];
        s1 += sp * t;
        s2 += sp;
        s3 += st * p;
        s4 += st;
    }

    // warp reduce
    #pragma unroll
    for (int off = 16; off; off >>= 1) {
        s1 += __shfl_down_sync(0xffffffffu, s1, off);
        s2 += __shfl_down_sync(0xffffffffu, s2, off);
        s3 += __shfl_down_sync(0xffffffffu, s3, off);
        s4 += __shfl_down_sync(0xffffffffu, s4, off);
    }
    __shared__ float red[8][4];
    int warp = threadIdx.x >> 5, lane = threadIdx.x & 31;
    if (lane == 0) {
        red[warp][0] = s1; red[warp][1] = s2; red[warp][2] = s3; red[warp][3] = s4;
    }
    __syncthreads();
    if (threadIdx.x < 4) {
        float s = 0.f;
        #pragma unroll
        for (int w = 0; w < 8; w++) s += red[w][threadIdx.x];
        atomicAdd(&g_sums[plane * 4 + threadIdx.x], s);
    }
}

__global__ void finalize_kernel(float* __restrict__ out) {
    if (threadIdx.x == 0 && blockIdx.x == 0) {
        const float eps = 1e-6f;
        float total = 0.f;
        #pragma unroll
        for (int pl = 0; pl < NPLANES; pl++) {
            float spt = g_sums[pl * 4 + 0];
            float sp  = g_sums[pl * 4 + 1];
            float stp = g_sums[pl * 4 + 2];
            float st  = g_sums[pl * 4 + 3];
            float tprec = spt / (sp + eps);
            float tsens = stp / (st + eps);
            float cl = 1.0f - 2.0f * tprec * tsens / (tprec + tsens + eps);
            total += cl;
        }
        out[0] = total * (1.0f / (float)NPLANES);
    }
}

extern "C" void kernel_launch(void* const* d_in, const int* in_sizes, int n_in,
                              void* d_out, int out_size)
{
    (void)in_sizes; (void)n_in; (void)out_size;
    const float* pred   = (const float*)d_in[0];
    const float* target = (const float*)d_in[1];
    float* out = (float*)d_out;

    zero_sums_kernel<<<1, 64>>>();

    dim3 grid(IMG_W / TILE, IMG_H / TILE, NPLANES * 2);
    dim3 blk(32, 8);
    for (int k = 0; k < NSTEPS; k++) {
        iter_kernel<<<grid, blk>>>(pred, target, k);
    }

    reduce_kernel<<<dim3(256, NPLANES), 256>>>(pred, target);
    finalize_kernel<<<1, 32>>>(out);
}

// round 4
// speedup vs baseline: 1.5017x; 1.5017x over previous
#include <cuda_runtime.h>

// SoftCLDiceLoss on [8,2,1024,1024]:
//   p = sigmoid(pred), t = clip(target,0,1)
//   skel(x) = 1 - prod_{k=0..10} (1 - relu(E_k - dilate(E_{k+1}))),  E_k = erode^k(x)
//   erode = 3x3 min (pad +inf), dilate = 3x3 max (pad -inf)
//   tprec = sum(skel_p*t)/(sum(skel_p)+eps); tsens = sum(skel_t*p)/(sum(skel_t)+eps)
//   loss = mean(1 - 2*tprec*tsens/(tprec+tsens+eps))
//
// Implementation: warp-strip register sweep, 2 erosion steps fused per kernel.
// No shared memory, no syncthreads in the morphology kernels.

#define IMG_W    1024
#define IMG_H    1024
#define NPLANES  16            // B*C
#define PLANE_SZ (IMG_W * IMG_H)

#define STRIP      128         // rows per warp sweep
#define PAIR_COLS  26          // 32 lanes - 2*3 halo
#define PAIR_TILES 40          // ceil(1024/26)
#define SGL_COLS   28          // 32 lanes - 2*2 halo
#define SGL_TILES  37          // ceil(1024/28)

// Scratch (device globals; allocations forbidden).
__device__ float g_E[2][2][NPLANES * PLANE_SZ];   // [skel(p/t)][pingpong]
__device__ float g_acc[2][NPLANES * PLANE_SZ];    // running prod(1 - delta)
__device__ float g_sums[NPLANES * 4];

__device__ __forceinline__ float min3f(float a, float b, float c) { return fminf(a, fminf(b, c)); }
__device__ __forceinline__ float max3f(float a, float b, float c) { return fmaxf(a, fmaxf(b, c)); }
__device__ __forceinline__ float sigmoidf(float x) { return 1.0f / (1.0f + __expf(-x)); }

__device__ __forceinline__ float hmin3(float v) {
    float l = __shfl_up_sync(0xffffffffu, v, 1);
    float r = __shfl_down_sync(0xffffffffu, v, 1);
    return min3f(l, v, r);
}
__device__ __forceinline__ float hmax3(float v) {
    float l = __shfl_up_sync(0xffffffffu, v, 1);
    float r = __shfl_down_sync(0xffffffffu, v, 1);
    return max3f(l, v, r);
}

__global__ void zero_sums_kernel() {
    int i = threadIdx.x;
    if (i < NPLANES * 4) g_sums[i] = 0.0f;
}

// Fused pair: reads E_k (k even), writes E_{k+2}, acc *= (1-d_k)(1-d_{k+1}).
// Lane validity: a all, h1/e1 lanes 1..30, h1d/d1/h2/e2 lanes 2..29,
// h2d/d2 lanes 3..28 == output lanes.
template<bool FIRST>
__global__ __launch_bounds__(128) void pair_kernel(
    const float* __restrict__ pred,
    const float* __restrict__ target,
    int srcbuf, int dstbuf)
{
    const int z     = blockIdx.z;
    const int skel  = z >> 4;
    const int plane = z & 15;
    const int wtile = blockIdx.x * 4 + (threadIdx.x >> 5);
    if (wtile >= PAIR_TILES) return;
    const int  lane = threadIdx.x & 31;
    const int  gx   = wtile * PAIR_COLS - 3 + lane;
    const bool inX  = (unsigned)gx < (unsigned)IMG_W;
    const bool outL = (lane >= 3) & (lane <= 28) & inX;
    const int  y0   = blockIdx.y * STRIP;

    const size_t pbase = (size_t)plane * PLANE_SZ;
    const float* __restrict__ src = FIRST ? ((skel ? target : pred) + pbase)
                                          : (&g_E[skel][srcbuf][pbase]);
    float* __restrict__ dst = &g_E[skel][dstbuf][pbase];
    float* __restrict__ acc = &g_acc[skel][pbase];

    float h1_m1 = 0.f, h1_m2 = 0.f, h1d_m1 = 0.f, h1d_m2 = 0.f;
    float h2_m1 = 0.f, h2_m2 = 0.f, h2d_m1 = 0.f, h2d_m2 = 0.f;
    float a_d1 = 0.f, a_d2 = 0.f, e1_d1 = 0.f, e1_d2 = 0.f, mk_d1 = 0.f;

    #pragma unroll 2
    for (int r = y0 - 3; r <= y0 + STRIP + 2; ++r) {
        // ---- load row r of E_k (+inf pad) ----
        float a = 1e30f;
        if (((unsigned)r < (unsigned)IMG_H) & inX) {
            float x = src[(size_t)r * IMG_W + gx];
            a = FIRST ? (skel ? fminf(fmaxf(x, 0.f), 1.f) : sigmoidf(x)) : x;
        }
        float h1 = hmin3(a);                              // row r
        float e1 = min3f(h1_m2, h1_m1, h1);               // E_{k+1}, row r-1
        bool  me1 = ((unsigned)(r - 1) < (unsigned)IMG_H) & inX;
        float e1d = me1 ? e1 : -1e30f;                    // dilate pad
        float e1e = me1 ? e1 :  1e30f;                    // erode pad
        float h1d = hmax3(e1d);                           // row r-1
        float h2  = hmin3(e1e);                           // row r-1
        float d1  = max3f(h1d_m2, h1d_m1, h1d);           // dilate(E_{k+1}), row r-2
        float mk  = 1.f - fmaxf(a_d2 - d1, 0.f);          // (1 - delta_k), row r-2
        float e2  = min3f(h2_m2, h2_m1, h2);              // E_{k+2}, row r-2
        int   re2 = r - 2;
        bool  rowe2 = (unsigned)re2 < (unsigned)IMG_H;
        if (outL & (re2 >= y0) & (re2 < y0 + STRIP))
            dst[(size_t)re2 * IMG_W + gx] = e2;
        float e2d = (rowe2 & inX) ? e2 : -1e30f;
        float h2d = hmax3(e2d);                           // row r-2
        float d2  = max3f(h2d_m2, h2d_m1, h2d);           // dilate(E_{k+2}), row r-3
        float dl2 = fmaxf(e1_d2 - d2, 0.f);               // delta_{k+1}, row r-3
        int   ro = r - 3;
        if (outL & (ro >= y0) & (ro < y0 + STRIP)) {
            float m = mk_d1 * (1.f - dl2);
            size_t g = (size_t)ro * IMG_W + gx;
            acc[g] = FIRST ? m : acc[g] * m;
        }
        // rotate windows
        h1_m2 = h1_m1;  h1_m1 = h1;
        h1d_m2 = h1d_m1; h1d_m1 = h1d;
        h2_m2 = h2_m1;  h2_m1 = h2;
        h2d_m2 = h2d_m1; h2d_m1 = h2d;
        a_d2 = a_d1;    a_d1 = a;
        e1_d2 = e1_d1;  e1_d1 = e1;
        mk_d1 = mk;
    }
}

// Final single step k=10: acc *= (1 - delta_10). No E_{11} store.
__global__ __launch_bounds__(128) void single_kernel(int srcbuf)
{
    const int z     = blockIdx.z;
    const int skel  = z >> 4;
    const int plane = z & 15;
    const int wtile = blockIdx.x * 4 + (threadIdx.x >> 5);
    if (wtile >= SGL_TILES) return;
    const int  lane = threadIdx.x & 31;
    const int  gx   = wtile * SGL_COLS - 2 + lane;
    const bool inX  = (unsigned)gx < (unsigned)IMG_W;
    const bool outL = (lane >= 2) & (lane <= 29) & inX;
    const int  y0   = blockIdx.y * STRIP;

    const size_t pbase = (size_t)plane * PLANE_SZ;
    const float* __restrict__ src = &g_E[skel][srcbuf][pbase];
    float* __restrict__ acc = &g_acc[skel][pbase];

    float h1_m1 = 0.f, h1_m2 = 0.f, h1d_m1 = 0.f, h1d_m2 = 0.f;
    float a_d1 = 0.f, a_d2 = 0.f;

    #pragma unroll 2
    for (int r = y0 - 2; r <= y0 + STRIP + 1; ++r) {
        float a = 1e30f;
        if (((unsigned)r < (unsigned)IMG_H) & inX)
            a = src[(size_t)r * IMG_W + gx];
        float h1 = hmin3(a);                              // row r
        float e1 = min3f(h1_m2, h1_m1, h1);               // E_{11}, row r-1
        bool  me1 = ((unsigned)(r - 1) < (unsigned)IMG_H) & inX;
        float e1d = me1 ? e1 : -1e30f;
        float h1d = hmax3(e1d);                           // row r-1
        float d1  = max3f(h1d_m2, h1d_m1, h1d);           // row r-2
        float dl  = fmaxf(a_d2 - d1, 0.f);                // delta_10, row r-2
        int   ro = r - 2;
        if (outL & (ro >= y0) & (ro < y0 + STRIP)) {
            size_t g = (size_t)ro * IMG_W + gx;
            acc[g] = acc[g] * (1.f - dl);
        }
        h1_m2 = h1_m1;  h1_m1 = h1;
        h1d_m2 = h1d_m1; h1d_m1 = h1d;
        a_d2 = a_d1;    a_d1 = a;
    }
}

// Per-plane sums via float4: {sum(sp*t), sum(sp), sum(st*p), sum(st)}
__global__ __launch_bounds__(256) void reduce_kernel(
    const float* __restrict__ pred,
    const float* __restrict__ target)
{
    const int plane = blockIdx.y;
    const size_t base = (size_t)plane * PLANE_SZ;
    const float4* __restrict__ p4 = (const float4*)(pred + base);
    const float4* __restrict__ t4 = (const float4*)(target + base);
    const float4* __restrict__ a04 = (const float4*)(&g_acc[0][base]);
    const float4* __restrict__ a14 = (const float4*)(&g_acc[1][base]);
    const int n4 = PLANE_SZ / 4;

    float s1 = 0.f, s2 = 0.f, s3 = 0.f, s4 = 0.f;
    for (int i = blockIdx.x * 256 + threadIdx.x; i < n4; i += 128 * 256) {
        float4 pv = p4[i], tv = t4[i], av = a04[i], bv = a14[i];
        float p0 = sigmoidf(pv.x), p1 = sigmoidf(pv.y), p2 = sigmoidf(pv.z), p3 = sigmoidf(pv.w);
        float sp0 = 1.f - av.x, sp1 = 1.f - av.y, sp2 = 1.f - av.z, sp3 = 1.f - av.w;
        float st0 = 1.f - bv.x, st1 = 1.f - bv.y, st2 = 1.f - bv.z, st3 = 1.f - bv.w;
        s1 += sp0 * tv.x + sp1 * tv.y + sp2 * tv.z + sp3 * tv.w;
        s2 += sp0 + sp1 + sp2 + sp3;
        s3 += st0 * p0 + st1 * p1 + st2 * p2 + st3 * p3;
        s4 += st0 + st1 + st2 + st3;
    }

    #pragma unroll
    for (int off = 16; off; off >>= 1) {
        s1 += __shfl_down_sync(0xffffffffu, s1, off);
        s2 += __shfl_down_sync(0xffffffffu, s2, off);
        s3 += __shfl_down_sync(0xffffffffu, s3, off);
        s4 += __shfl_down_sync(0xffffffffu, s4, off);
    }
    __shared__ float red[8][4];
    int warp = threadIdx.x >> 5, lane = threadIdx.x & 31;
    if (lane == 0) { red[warp][0] = s1; red[warp][1] = s2; red[warp][2] = s3; red[warp][3] = s4; }
    __syncthreads();
    if (threadIdx.x < 4) {
        float s = 0.f;
        #pragma unroll
        for (int w = 0; w < 8; w++) s += red[w][threadIdx.x];
        atomicAdd(&g_sums[plane * 4 + threadIdx.x], s);
    }
}

__global__ void finalize_kernel(float* __restrict__ out) {
    if (threadIdx.x == 0 && blockIdx.x == 0) {
        const float eps = 1e-6f;
        float total = 0.f;
        #pragma unroll
        for (int pl = 0; pl < NPLANES; pl++) {
            float spt = g_sums[pl * 4 + 0];
            float sp  = g_sums[pl * 4 + 1];
            float stp = g_sums[pl * 4 + 2];
            float st  = g_sums[pl * 4 + 3];
            float tprec = spt / (sp + eps);
            float tsens = stp / (st + eps);
            total += 1.0f - 2.0f * tprec * tsens / (tprec + tsens + eps);
        }
        out[0] = total * (1.0f / (float)NPLANES);
    }
}

extern "C" void kernel_launch(void* const* d_in, const int* in_sizes, int n_in,
                              void* d_out, int out_size)
{
    (void)in_sizes; (void)n_in; (void)out_size;
    const float* pred   = (const float*)d_in[0];
    const float* target = (const float*)d_in[1];
    float* out = (float*)d_out;

    zero_sums_kernel<<<1, 64>>>();

    dim3 pgrid((PAIR_TILES + 3) / 4, IMG_H / STRIP, NPLANES * 2);  // 10 x 8 x 32
    dim3 sgrid((SGL_TILES + 3) / 4, IMG_H / STRIP, NPLANES * 2);   // 10 x 8 x 32
    dim3 blk(128);

    // pairs: (0,1)->E2 buf0, (2,3)->E4 buf1, (4,5)->E6 buf0, (6,7)->E8 buf1, (8,9)->E10 buf0
    pair_kernel<true ><<<pgrid, blk>>>(pred, target, 0, 0);
    pair_kernel<false><<<pgrid, blk>>>(pred, target, 0, 1);
    pair_kernel<false><<<pgrid, blk>>>(pred, target, 1, 0);
    pair_kernel<false><<<pgrid, blk>>>(pred, target, 0, 1);
    pair_kernel<false><<<pgrid, blk>>>(pred, target, 1, 0);
    single_kernel<<<sgrid, blk>>>(0);

    reduce_kernel<<<dim3(128, NPLANES), 256>>>(pred, target);
    finalize_kernel<<<1, 32>>>(out);
}

// round 6
// speedup vs baseline: 2.9419x; 1.9590x over previous
#include <cuda_runtime.h>

// SoftCLDiceLoss on [8,2,1024,1024]:
//   p = sigmoid(pred), t = target
//   skel(x) = 1 - prod_{k=0..10} (1 - relu(E_k - dilate(E_{k+1}))),  E_k = erode^k(clip(x))
//   erode = 3x3 min (pad +inf), dilate = 3x3 max (pad -inf)
//   tprec = sum(skel_p*t)/(sum(skel_p)+eps); tsens = sum(skel_t*p)/(sum(skel_t)+eps)
//   loss = mean(1 - 2*tprec*tsens/(tprec+tsens+eps))
//
// Warp-strip register sweep, 3 erosion steps fused per kernel (halo 4),
// final 2 steps fused with the global reduction. Depth-4 software prefetch
// pipelines for input rows, acc, and the paired input. No shared memory in
// the morphology kernels.

#define IMG_W    1024
#define IMG_H    1024
#define NPLANES  16
#define PLANE_SZ (IMG_W * IMG_H)

#define STRIP   128
#define COLS3   24             // 32 - 2*4 halo (triple kernel)
#define TILES3  43             // ceil(1024/24)
#define COLS2   26             // 32 - 2*3 halo (final pair kernel)
#define TILES2  40             // ceil(1024/26)

__device__ float g_E[2][2][NPLANES * PLANE_SZ];   // [skel][pingpong]
__device__ float g_acc[2][NPLANES * PLANE_SZ];
__device__ float g_sums[NPLANES * 4];

__device__ __forceinline__ float min3f(float a, float b, float c) { return fminf(a, fminf(b, c)); }
__device__ __forceinline__ float max3f(float a, float b, float c) { return fmaxf(a, fmaxf(b, c)); }
__device__ __forceinline__ float sigmoidf(float x) { return 1.0f / (1.0f + __expf(-x)); }

__device__ __forceinline__ float hmin3(float v) {
    float l = __shfl_up_sync(0xffffffffu, v, 1);
    float r = __shfl_down_sync(0xffffffffu, v, 1);
    return min3f(l, v, r);
}
__device__ __forceinline__ float hmax3(float v) {
    float l = __shfl_up_sync(0xffffffffu, v, 1);
    float r = __shfl_down_sync(0xffffffffu, v, 1);
    return max3f(l, v, r);
}

__global__ void zero_sums_kernel() {
    int i = threadIdx.x;
    if (i < NPLANES * 4) g_sums[i] = 0.0f;
}

// ---------------------------------------------------------------------------
// Triple kernel: reads E_k, writes E_{k+3}, acc *= Π_{s=k..k+2} (1 - delta_s).
// Lane validity: a all; e1 lanes 1..30; d1,e2 lanes 2..29; d2,e3 lanes 3..28;
// d3 lanes 4..27 == output lanes.
// ---------------------------------------------------------------------------
template<bool FIRST>
__global__ __launch_bounds__(128) void triple_kernel(
    const float* __restrict__ pred,
    const float* __restrict__ target,
    int srcbuf, int dstbuf)
{
    const int z     = blockIdx.z;
    const int skel  = z >> 4;
    const int plane = z & 15;
    const int wtile = blockIdx.x * 4 + (threadIdx.x >> 5);
    if (wtile >= TILES3) return;
    const int  lane = threadIdx.x & 31;
    const int  gx   = wtile * COLS3 - 4 + lane;
    const bool inX  = (unsigned)gx < (unsigned)IMG_W;
    const bool outL = (lane >= 4) & (lane <= 27) & inX;
    const int  y0   = blockIdx.y * STRIP;
    const int  yEnd = y0 + STRIP;

    const size_t pbase = (size_t)plane * PLANE_SZ;
    const float* __restrict__ src = FIRST ? ((skel ? target : pred) + pbase)
                                          : (&g_E[skel][srcbuf][pbase]);
    float* __restrict__ dst = &g_E[skel][dstbuf][pbase];
    float* __restrict__ acc = &g_acc[skel][pbase];

    auto ldrow = [&](int rr) -> float {
        float v = 1e30f;
        if (((unsigned)rr < (unsigned)IMG_H) & inX) {
            float x = __ldg(&src[(size_t)rr * IMG_W + gx]);
            v = FIRST ? (skel ? __saturatef(x) : sigmoidf(x)) : x;
        }
        return v;
    };

    float abuf[4];
    float accbuf[4] = {0.f, 0.f, 0.f, 0.f};
    #pragma unroll
    for (int j = 0; j < 4; j++) abuf[j] = ldrow(y0 - 4 + j);

    float h1m1=0,h1m2=0,h1dm1=0,h1dm2=0;
    float h2m1=0,h2m2=0,h2dm1=0,h2dm2=0;
    float h3m1=0,h3m2=0,h3dm1=0,h3dm2=0;
    float ad1=0,ad2=0,e1d1=0,e1d2=0,e2d1=0,e2d2=0;
    float mk0d1=0,mk0d2=0,mk1d1=0;

    // rows y0-4 .. y0+STRIP+3; rb ≡ y0-4 (mod 4) so slot index == j everywhere.
    for (int rb = y0 - 4; rb <= yEnd; rb += 4) {
        #pragma unroll
        for (int j = 0; j < 4; j++) {
            const int r = rb + j;
            float a = abuf[j];
            abuf[j] = ldrow(r + 4);                 // consumed 4 iters later
            float av = 0.f;
            if (!FIRST) {
                av = accbuf[j];                     // acc row r-4
                if ((r >= y0) & (r < yEnd) & outL)
                    accbuf[j] = acc[(size_t)r * IMG_W + gx];   // 4-iter slack
            }

            float h1 = hmin3(a);                              // row r
            float e1 = min3f(h1m2, h1m1, h1);                 // E_{k+1}, row r-1
            bool  m1 = ((unsigned)(r - 1) < (unsigned)IMG_H) & inX;
            float h1d = hmax3(m1 ? e1 : -1e30f);              // row r-1
            float h2  = hmin3(m1 ? e1 :  1e30f);              // row r-1
            float d1  = max3f(h1dm2, h1dm1, h1d);             // dilate(E_{k+1}), r-2
            float mk0 = 1.f - fmaxf(ad2 - d1, 0.f);           // 1-delta_k, r-2
            float e2  = min3f(h2m2, h2m1, h2);                // E_{k+2}, r-2
            bool  m2 = ((unsigned)(r - 2) < (unsigned)IMG_H) & inX;
            float h2d = hmax3(m2 ? e2 : -1e30f);              // r-2
            float h3  = hmin3(m2 ? e2 :  1e30f);              // r-2
            float d2  = max3f(h2dm2, h2dm1, h2d);             // dilate(E_{k+2}), r-3
            float mk1 = 1.f - fmaxf(e1d2 - d2, 0.f);          // 1-delta_{k+1}, r-3
            float e3  = min3f(h3m2, h3m1, h3);                // E_{k+3}, r-3
            bool  m3 = ((unsigned)(r - 3) < (unsigned)IMG_H) & inX;
            if (outL & (r - 3 >= y0) & (r - 3 < yEnd))
                dst[(size_t)(r - 3) * IMG_W + gx] = e3;
            float h3d = hmax3(m3 ? e3 : -1e30f);              // r-3
            float d3  = max3f(h3dm2, h3dm1, h3d);             // dilate(E_{k+3}), r-4
            float mk2 = 1.f - fmaxf(e2d2 - d3, 0.f);          // 1-delta_{k+2}, r-4
            const int ro = r - 4;
            if (outL & (ro >= y0) & (ro < yEnd)) {
                float m = mk0d2 * mk1d1 * mk2;
                acc[(size_t)ro * IMG_W + gx] = FIRST ? m : av * m;
            }
            h1m2=h1m1;  h1m1=h1;  h1dm2=h1dm1; h1dm1=h1d;
            h2m2=h2m1;  h2m1=h2;  h2dm2=h2dm1; h2dm1=h2d;
            h3m2=h3m1;  h3m1=h3;  h3dm2=h3dm1; h3dm1=h3d;
            ad2=ad1;   ad1=a;   e1d2=e1d1;  e1d1=e1;  e2d2=e2d1; e2d1=e2;
            mk0d2=mk0d1; mk0d1=mk0; mk1d1=mk1;
        }
    }
}

// ---------------------------------------------------------------------------
// Final kernel: steps 9,10 fused with the reduction. Reads E9 + acc + paired
// input, produces per-plane {sum(skel*other), sum(skel)} via atomics.
// Halo 3; output lanes 3..28.
// ---------------------------------------------------------------------------
__global__ __launch_bounds__(128) void final_kernel(
    const float* __restrict__ pred,
    const float* __restrict__ target,
    int srcbuf)
{
    const int z     = blockIdx.z;
    const int skel  = z >> 4;
    const int plane = z & 15;
    const int wtile = blockIdx.x * 4 + (threadIdx.x >> 5);
    const int  lane = threadIdx.x & 31;
    const int  y0   = blockIdx.y * STRIP;
    const int  yEnd = y0 + STRIP;

    float s_num = 0.f, s_den = 0.f;

    if (wtile < TILES2) {
        const int  gx   = wtile * COLS2 - 3 + lane;
        const bool inX  = (unsigned)gx < (unsigned)IMG_W;
        const bool outL = (lane >= 3) & (lane <= 28) & inX;

        const size_t pbase = (size_t)plane * PLANE_SZ;
        const float* __restrict__ src   = &g_E[skel][srcbuf][pbase];
        const float* __restrict__ acc   = &g_acc[skel][pbase];
        // skel_p (skel=0) pairs with raw target; skel_t pairs with sigmoid(pred)
        const float* __restrict__ other = (skel ? pred : target) + pbase;

        auto ldrow = [&](int rr) -> float {
            float v = 1e30f;
            if (((unsigned)rr < (unsigned)IMG_H) & inX)
                v = __ldg(&src[(size_t)rr * IMG_W + gx]);
            return v;
        };

        float abuf[4];
        float accbuf[4] = {0.f, 0.f, 0.f, 0.f};
        float obuf[4]   = {0.f, 0.f, 0.f, 0.f};
        #pragma unroll
        for (int j = 0; j < 4; j++) abuf[j] = ldrow(y0 - 4 + j);

        float h1m1=0,h1m2=0,h1dm1=0,h1dm2=0;
        float h2m1=0,h2m2=0,h2dm1=0,h2dm2=0;
        float ad1=0,ad2=0,e1d1=0,e1d2=0,mkd1=0;

        for (int rb = y0 - 4; rb <= yEnd; rb += 4) {
            #pragma unroll
            for (int j = 0; j < 4; j++) {
                const int r = rb + j;
                float a = abuf[j];
                abuf[j] = ldrow(r + 4);
                // consume row r-3 (slot (j+1)&3), prefetch row r (slot j)
                float av = accbuf[(j + 1) & 3];
                float ov = obuf[(j + 1) & 3];
                if ((r >= y0) & (r < yEnd) & outL) {
                    size_t g = (size_t)r * IMG_W + gx;
                    accbuf[j] = acc[g];
                    obuf[j]   = __ldg(&other[g]);
                }

                float h1 = hmin3(a);                          // row r (E9)
                float e1 = min3f(h1m2, h1m1, h1);             // E10, row r-1
                bool  m1 = ((unsigned)(r - 1) < (unsigned)IMG_H) & inX;
                float h1d = hmax3(m1 ? e1 : -1e30f);
                float h2  = hmin3(m1 ? e1 :  1e30f);
                float d1  = max3f(h1dm2, h1dm1, h1d);         // dilate(E10), r-2
                float mk  = 1.f - fmaxf(ad2 - d1, 0.f);       // 1-delta9, r-2
                float e2  = min3f(h2m2, h2m1, h2);            // E11, r-2
                bool  m2 = ((unsigned)(r - 2) < (unsigned)IMG_H) & inX;
                float h2d = hmax3(m2 ? e2 : -1e30f);
                float d2  = max3f(h2dm2, h2dm1, h2d);         // dilate(E11), r-3
                float dl  = fmaxf(e1d2 - d2, 0.f);            // delta10, r-3
                const int ro = r - 3;
                if (outL & (ro >= y0) & (ro < yEnd)) {
                    float sp = 1.f - av * (mkd1 * (1.f - dl));   // skeleton value
                    s_num += sp * (skel ? sigmoidf(ov) : ov);
                    s_den += sp;
                }
                h1m2=h1m1;  h1m1=h1;  h1dm2=h1dm1; h1dm1=h1d;
                h2m2=h2m1;  h2m1=h2;  h2dm2=h2dm1; h2dm1=h2d;
                ad2=ad1;   ad1=a;   e1d2=e1d1;  e1d1=e1;  mkd1=mk;
            }
        }
    }

    // warp reduce
    #pragma unroll
    for (int off = 16; off; off >>= 1) {
        s_num += __shfl_down_sync(0xffffffffu, s_num, off);
        s_den += __shfl_down_sync(0xffffffffu, s_den, off);
    }
    __shared__ float red[4][2];
    int warp = threadIdx.x >> 5;
    if ((threadIdx.x & 31) == 0) { red[warp][0] = s_num; red[warp][1] = s_den; }
    __syncthreads();
    if (threadIdx.x < 2) {
        float s = red[0][threadIdx.x] + red[1][threadIdx.x]
                + red[2][threadIdx.x] + red[3][threadIdx.x];
        atomicAdd(&g_sums[plane * 4 + skel * 2 + threadIdx.x], s);
    }
}

__global__ void finalize_kernel(float* __restrict__ out) {
    if (threadIdx.x == 0 && blockIdx.x == 0) {
        const float eps = 1e-6f;
        float total = 0.f;
        #pragma unroll
        for (int pl = 0; pl < NPLANES; pl++) {
            float spt = g_sums[pl * 4 + 0];
            float sp  = g_sums[pl * 4 + 1];
            float stp = g_sums[pl * 4 + 2];
            float st  = g_sums[pl * 4 + 3];
            float tprec = spt / (sp + eps);
            float tsens = stp / (st + eps);
            total += 1.0f - 2.0f * tprec * tsens / (tprec + tsens + eps);
        }
        out[0] = total * (1.0f / (float)NPLANES);
    }
}

extern "C" void kernel_launch(void* const* d_in, const int* in_sizes, int n_in,
                              void* d_out, int out_size)
{
    (void)in_sizes; (void)n_in; (void)out_size;
    const float* pred   = (const float*)d_in[0];
    const float* target = (const float*)d_in[1];
    float* out = (float*)d_out;

    zero_sums_kernel<<<1, 64>>>();

    dim3 tgrid((TILES3 + 3) / 4, IMG_H / STRIP, NPLANES * 2);   // 11 x 8 x 32
    dim3 fgrid((TILES2 + 3) / 4, IMG_H / STRIP, NPLANES * 2);   // 10 x 8 x 32
    dim3 blk(128);

    // steps 0-2 -> E3 (buf0); 3-5 -> E6 (buf1); 6-8 -> E9 (buf0); 9-10 + reduce
    triple_kernel<true ><<<tgrid, blk>>>(pred, target, 0, 0);
    triple_kernel<false><<<tgrid, blk>>>(pred, target, 0, 1);
    triple_kernel<false><<<tgrid, blk>>>(pred, target, 1, 0);
    final_kernel<<<fgrid, blk>>>(pred, target, 0);

    finalize_kernel<<<1, 32>>>(out);
}